// round 12
// baseline (speedup 1.0000x reference)
#include <cuda_runtime.h>
#include <math.h>

#define BB 16
#define NN 512
#define CC 512
#define NS 16
#define CM 64           // CC / S
#define ROWS (BB*NN)    // 8192

typedef unsigned long long ull;

__device__ __forceinline__ void ffma2(ull &d, ull a, ull b) {
    asm("fma.rn.f32x2 %0, %1, %2, %0;" : "+l"(d) : "l"(a), "l"(b));
}
__device__ __forceinline__ ull pack2(float lo, float hi) {
    ull r; asm("mov.b64 %0, {%1, %2};" : "=l"(r) : "f"(lo), "f"(hi)); return r;
}
__device__ __forceinline__ void unpack2(float &lo, float &hi, ull v) {
    asm("mov.b64 {%0, %1}, %2;" : "=f"(lo), "=f"(hi) : "l"(v));
}

// ---------------- scratch (static device globals; no allocation) -------------
__device__ float g_xq[ROWS*CC];
__device__ float g_xk[ROWS*CC];
__device__ float g_xv[ROWS*CC];
__device__ int   g_idx[ROWS*NS];

// ================= stage1: fused QKV GEMM + kNN in one launch ================
#define QKV_BLOCKS 768

__global__ __launch_bounds__(256) void stage1_kernel(
    const float* __restrict__ p,
    const float* __restrict__ x,
    const float* __restrict__ Wq, const float* __restrict__ bq,
    const float* __restrict__ Wk, const float* __restrict__ bk,
    const float* __restrict__ Wv, const float* __restrict__ bv)
{
    __shared__ __align__(16) float smem_u[2 * 16 * 132];

    if (blockIdx.x < QKV_BLOCKS) {
        float (*As)[132] = reinterpret_cast<float(*)[132]>(smem_u);
        float (*Bs)[132] = reinterpret_cast<float(*)[132]>(smem_u + 16*132);

        const int z    = blockIdx.x >> 8;
        const int tile = blockIdx.x & 255;
        const float* W; const float* bias; float* out;
        if (z == 0)      { W = Wq; bias = bq; out = g_xq; }
        else if (z == 1) { W = Wk; bias = bk; out = g_xk; }
        else             { W = Wv; bias = bv; out = g_xv; }

        const int tid = threadIdx.x;
        const int tx = tid & 15;
        const int ty = tid >> 4;
        const int m0 = (tile >> 2) * 128;
        const int c0 = (tile & 3) * 128;
        const int b  = m0 >> 9;
        const int n0 = m0 & 511;
        const float* xb = x + (size_t)b * CC * NN;

        ull acc[8][4];
#pragma unroll
        for (int i = 0; i < 8; i++)
#pragma unroll
            for (int j = 0; j < 4; j++) acc[i][j] = 0ULL;

        for (int k0 = 0; k0 < CC; k0 += 16) {
#pragma unroll
            for (int i = 0; i < 2; i++) {
                int f  = tid + i*256;
                int kk = f >> 5;
                int mm = (f & 31) * 4;
                *reinterpret_cast<float4*>(&As[kk][mm]) =
                    *reinterpret_cast<const float4*>(&xb[(size_t)(k0+kk)*NN + n0 + mm]);
                *reinterpret_cast<float4*>(&Bs[kk][mm]) =
                    *reinterpret_cast<const float4*>(&W[(size_t)(k0+kk)*CC + c0 + mm]);
            }
            __syncthreads();
#pragma unroll
            for (int kk = 0; kk < 16; kk++) {
                float4 a0 = *reinterpret_cast<const float4*>(&As[kk][ty*4]);
                float4 a1 = *reinterpret_cast<const float4*>(&As[kk][64 + ty*4]);
                ulonglong2 bp01 = *reinterpret_cast<const ulonglong2*>(&Bs[kk][tx*4]);
                ulonglong2 bp23 = *reinterpret_cast<const ulonglong2*>(&Bs[kk][64 + tx*4]);
                float av[8] = {a0.x,a0.y,a0.z,a0.w, a1.x,a1.y,a1.z,a1.w};
#pragma unroll
                for (int i = 0; i < 8; i++) {
                    ull ad = pack2(av[i], av[i]);
                    ffma2(acc[i][0], ad, bp01.x);
                    ffma2(acc[i][1], ad, bp01.y);
                    ffma2(acc[i][2], ad, bp23.x);
                    ffma2(acc[i][3], ad, bp23.y);
                }
            }
            __syncthreads();
        }

#pragma unroll
        for (int i = 0; i < 8; i++) {
            int row = m0 + ((i < 4) ? (ty*4 + i) : (64 + ty*4 + i - 4));
#pragma unroll
            for (int jh = 0; jh < 2; jh++) {
                int c = c0 + ((jh == 0) ? (tx*4) : (64 + tx*4));
                float e0,e1,e2,e3;
                unpack2(e0, e1, acc[i][jh*2+0]);
                unpack2(e2, e3, acc[i][jh*2+1]);
                float4 v;
                v.x = e0 + bias[c+0];
                v.y = e1 + bias[c+1];
                v.z = e2 + bias[c+2];
                v.w = e3 + bias[c+3];
                *reinterpret_cast<float4*>(&out[(size_t)row*CC + c]) = v;
            }
        }
    } else {
        // kNN: warp per query; ulp-exact distances
        float* ps = smem_u;
        float* sq = smem_u + NN*3;
        const int kb   = blockIdx.x - QKV_BLOCKS;
        const int b    = kb >> 6;
        const int warp = threadIdx.x >> 5;
        const int lane = threadIdx.x & 31;
        const float* pb = p + (size_t)b * NN * 3;
        for (int i = threadIdx.x; i < NN*3; i += 256) ps[i] = pb[i];
        __syncthreads();
        for (int i = threadIdx.x; i < NN; i += 256) {
            float m0 = __fmul_rn(ps[i*3+0], ps[i*3+0]);
            float m1 = __fmul_rn(ps[i*3+1], ps[i*3+1]);
            float m2 = __fmul_rn(ps[i*3+2], ps[i*3+2]);
            sq[i] = __fadd_rn(__fadd_rn(m0, m1), m2);
        }
        __syncthreads();

        const int n = (kb & 63) * 8 + warp;
        const float px = ps[n*3+0], py = ps[n*3+1], pz = ps[n*3+2];
        const float sn = sq[n];

        float d[16];
#pragma unroll
        for (int i = 0; i < 16; i++) {
            int m = lane * 16 + i;
            float dot = __fmul_rn(px, ps[m*3+0]);
            dot = fmaf(py, ps[m*3+1], dot);
            dot = fmaf(pz, ps[m*3+2], dot);
            d[i] = __fsub_rn(__fadd_rn(sn, sq[m]), __fmul_rn(2.0f, dot));
        }

        const int row = b*NN + n;
        const float INF = __int_as_float(0x7f800000);
#pragma unroll 1
        for (int t = 0; t < NS; t++) {
            float bd = d[0]; int bi = 0;
#pragma unroll
            for (int i = 1; i < 16; i++) if (d[i] < bd) { bd = d[i]; bi = i; }
            int ib = __float_as_int(bd);
            unsigned u = (unsigned)ib ^ ((ib < 0) ? 0xFFFFFFFFu : 0x80000000u);
            ull key = ((ull)u << 32) | (unsigned)(lane*16 + bi);
#pragma unroll
            for (int s = 16; s > 0; s >>= 1) {
                ull o = __shfl_xor_sync(0xFFFFFFFFu, key, s);
                if (o < key) key = o;
            }
            int win_m = (int)(key & 0xFFFFFFFFu);
            if ((win_m >> 4) == lane) {
                int wi = win_m & 15;
#pragma unroll
                for (int i = 0; i < 16; i++) if (i == wi) d[i] = INF;
            }
            if (lane == 0) g_idx[row*NS + t] = win_m;
        }
    }
}

// ============================ main fused kernel ==============================
// 4 points per block, 2048 blocks, 256 threads, 2 blocks/SM.
// Phase B uses register-resident coefficients: thread owns fixed c4 across
// all 64 rows -> per output float4 only 1 LDG + 1 STS hit L1.
#define SM_AS   0
#define SM_WS   8448
#define SM_DS   17152
#define SM_S1   19200
#define SM_QS   19712
#define SM_H    21248
#define SM_IDX  21440
#define SM_TOT  21504   // floats -> 86016 bytes

__global__ __launch_bounds__(256, 2) void pt_main(
    const float* __restrict__ p,
    const float* __restrict__ p1W,  const float* __restrict__ p1b,
    const float* __restrict__ pbng, const float* __restrict__ pbnb,
    const float* __restrict__ p2W,  const float* __restrict__ p2b,
    const float* __restrict__ bn1g, const float* __restrict__ bn1bv,
    const float* __restrict__ W1,   const float* __restrict__ b1,
    const float* __restrict__ bn2g, const float* __restrict__ bn2bv,
    const float* __restrict__ W2,   const float* __restrict__ b2,
    float* __restrict__ out)
{
    extern __shared__ __align__(16) float sm[];
    float* aS  = sm + SM_AS;
    float* wS  = sm + SM_WS;
    float* DS  = sm + SM_DS;
    float* s1S = sm + SM_S1;
    float* QS  = sm + SM_QS;
    float* hS  = sm + SM_H;
    int*   idxS = (int*)(sm + SM_IDX);

    const int tid  = threadIdx.x;
    const int row0 = blockIdx.x * 4;
    const int b    = row0 >> 9;
    const float RS = rsqrtf(1.0f + 1e-5f);

    // ---- prologue ----
    if (tid < 64) {
        int pt = tid >> 4;
        int row = row0 + pt;
        int m = g_idx[row*NS + (tid & 15)];
        idxS[tid] = m;
        int gm = b*NN + m;
        float prx = p[gm*3+0] - p[row*3+0];
        float pry = p[gm*3+1] - p[row*3+1];
        float prz = p[gm*3+2] - p[row*3+2];
#pragma unroll
        for (int j = 0; j < 3; j++) {
            float v = prx*p1W[0*3+j] + pry*p1W[1*3+j] + prz*p1W[2*3+j] + p1b[j];
            v = v * (pbng[j] * RS) + pbnb[j];
            hS[tid*3+j] = fmaxf(v, 0.0f);
        }
    }
    // s1 and Q_i = p2W_i * s1  (c-indexed, shared across chunks)
    if (tid < 128) {
        int c4 = tid * 4;
        float4 g4 = *reinterpret_cast<const float4*>(&bn1g[c4]);
        float4 s14 = make_float4(g4.x*RS, g4.y*RS, g4.z*RS, g4.w*RS);
        *reinterpret_cast<float4*>(&s1S[c4]) = s14;
#pragma unroll
        for (int rsel = 0; rsel < 3; rsel++) {
            float4 q4 = *reinterpret_cast<const float4*>(&p2W[rsel*CC + c4]);
            q4.x *= s14.x; q4.y *= s14.y; q4.z *= s14.z; q4.w *= s14.w;
            *reinterpret_cast<float4*>(&QS[rsel*CC + c4]) = q4;
        }
    }
    // D[pt][c] = (p2b - xq)*s1 + o1
#pragma unroll
    for (int i = 0; i < 2; i++) {
        int s = tid + i*256;
        int pt = s >> 7, c4 = (s & 127) * 4;
        float4 xq4 = *reinterpret_cast<const float4*>(&g_xq[(size_t)(row0+pt)*CC + c4]);
        float4 pb4 = *reinterpret_cast<const float4*>(&p2b[c4]);
        float4 g4  = *reinterpret_cast<const float4*>(&bn1g[c4]);
        float4 o4  = *reinterpret_cast<const float4*>(&bn1bv[c4]);
        float4 Dv;
        Dv.x = (pb4.x - xq4.x) * (g4.x*RS) + o4.x;
        Dv.y = (pb4.y - xq4.y) * (g4.y*RS) + o4.y;
        Dv.z = (pb4.z - xq4.z) * (g4.z*RS) + o4.z;
        Dv.w = (pb4.w - xq4.w) * (g4.w*RS) + o4.w;
        *reinterpret_cast<float4*>(&DS[pt*512 + c4]) = Dv;
    }
    __syncthreads();

    // GEMM1 mapping: cg(8c) x jg(2 of 8j) x pt(4) x ks(4 of 32k)
    const int cg = tid & 7;
    const int jg = (tid >> 3) & 1;
    const int pt = (tid >> 4) & 3;
    const int ks = tid >> 6;

    // phase-B mapping: cq (32 float4-cols per 128k chunk) x rg (8 groups of 8 rows)
    const int cq  = tid & 31;
    const int rg  = tid >> 5;
    const int ptB = rg >> 1;                 // rows rg*8..rg*8+7 share one pt

    ull acc[8][4];
#pragma unroll
    for (int j = 0; j < 8; j++)
#pragma unroll
        for (int cp = 0; cp < 4; cp++) acc[j][cp] = 0ULL;

    for (int kc = 0; kc < 4; kc++) {
        // stage W1 chunk (128k x 64c), stride 68
#pragma unroll
        for (int i = 0; i < 8; i++) {
            int s = tid + i*256;
            int k = s >> 4, c4 = (s & 15) * 4;
            *reinterpret_cast<float4*>(&wS[k*68 + c4]) =
                *reinterpret_cast<const float4*>(&W1[(size_t)(kc*128 + k)*CM + c4]);
        }
        // phase B chunk: thread owns c4 = kc*128 + cq*4 for rows rg*8..rg*8+7
        {
            const int c = kc*128 + cq*4;
            float4 s14 = *reinterpret_cast<const float4*>(&s1S[c]);
            float4 Q04 = *reinterpret_cast<const float4*>(&QS[c]);
            float4 Q14 = *reinterpret_cast<const float4*>(&QS[CC + c]);
            float4 Q24 = *reinterpret_cast<const float4*>(&QS[2*CC + c]);
            float4 D4  = *reinterpret_cast<const float4*>(&DS[ptB*512 + c]);
            const int k4 = cq*4;
#pragma unroll
            for (int i = 0; i < 8; i++) {
                int r = rg*8 + i;
                int m = idxS[r];                     // warp-uniform broadcast
                float h0 = hS[r*3+0], h1 = hS[r*3+1], h2 = hS[r*3+2];
                float4 xk4 = *reinterpret_cast<const float4*>(
                    &g_xk[(size_t)(b*NN+m)*CC + c]);
                float4 res;
                res.x = fmaxf(fmaf(xk4.x, s14.x, fmaf(h0,Q04.x, fmaf(h1,Q14.x, fmaf(h2,Q24.x, D4.x)))), 0.0f);
                res.y = fmaxf(fmaf(xk4.y, s14.y, fmaf(h0,Q04.y, fmaf(h1,Q14.y, fmaf(h2,Q24.y, D4.y)))), 0.0f);
                res.z = fmaxf(fmaf(xk4.z, s14.z, fmaf(h0,Q04.z, fmaf(h1,Q14.z, fmaf(h2,Q24.z, D4.z)))), 0.0f);
                res.w = fmaxf(fmaf(xk4.w, s14.w, fmaf(h0,Q04.w, fmaf(h1,Q14.w, fmaf(h2,Q24.w, D4.w)))), 0.0f);
                *reinterpret_cast<float4*>(&aS[r*132 + k4]) = res;
            }
        }
        __syncthreads();

        // GEMM1 chunk: acc += a(8j x 32k-slice) @ W1(32k x 8c)
        {
            const float* aB = aS + (pt*16 + jg*8)*132 + ks*32;
            const float* wB = wS + (ks*32)*68 + cg*8;
#pragma unroll 2
            for (int k4 = 0; k4 < 32; k4 += 4) {
                float4 av[8];
#pragma unroll
                for (int j = 0; j < 8; j++)
                    av[j] = *reinterpret_cast<const float4*>(aB + j*132 + k4);
#pragma unroll
                for (int kk = 0; kk < 4; kk++) {
                    const float* wrow = wB + (k4+kk)*68;
                    ulonglong2 w01 = *reinterpret_cast<const ulonglong2*>(wrow);
                    ulonglong2 w23 = *reinterpret_cast<const ulonglong2*>(wrow + 4);
#pragma unroll
                    for (int j = 0; j < 8; j++) {
                        const float* af = (const float*)&av[j];
                        float a = af[kk];
                        ull ad = pack2(a, a);
                        ffma2(acc[j][0], ad, w01.x);
                        ffma2(acc[j][1], ad, w01.y);
                        ffma2(acc[j][2], ad, w23.x);
                        ffma2(acc[j][3], ad, w23.y);
                    }
                }
            }
        }
        __syncthreads();
    }

    // spill partials: ks 0/1 -> aS, ks 2/3 -> wS
    {
        float* dst = ((ks < 2) ? aS : wS) + (ks & 1) * 4096;
        int base = pt*1024 + jg*8*64 + cg*8;
#pragma unroll
        for (int j = 0; j < 8; j++) {
#pragma unroll
            for (int cp = 0; cp < 4; cp++) {
                float lo, hi;
                unpack2(lo, hi, acc[j][cp]);
                *reinterpret_cast<float2*>(&dst[base + j*64 + cp*2]) =
                    make_float2(lo, hi);
            }
        }
    }
    __syncthreads();

    // reduce 4 slices + bias + bn2 + relu
    float a2v[16];
#pragma unroll
    for (int i = 0; i < 16; i++) {
        int o = tid + i*256;
        int c = o & 63;
        float s = aS[o] + aS[4096 + o] + wS[o] + wS[4096 + o];
        s += b1[c];
        s = fmaf(s, bn2g[c]*RS, bn2bv[c]);
        a2v[i] = fmaxf(s, 0.0f);
    }
    __syncthreads();

    // write a2 (stride 68 rows in aS) + stage W2 into wS
#pragma unroll
    for (int i = 0; i < 16; i++) {
        int o = tid + i*256;
        int r = o >> 6, c = o & 63;
        aS[r*68 + c] = a2v[i];
    }
#pragma unroll
    for (int i = 0; i < 4; i++) {
        int s = tid + i*256;
        int k = s >> 4, c4 = (s & 15) * 4;
        *reinterpret_cast<float4*>(&wS[k*68 + c4]) =
            *reinterpret_cast<const float4*>(&W2[(size_t)k*CM + c4]);
    }
    __syncthreads();

    // ---- GEMM2: (64 rows x 64k) @ (64k x 64c); all 256 threads, 4 rows each --
    {
        const int cg2 = tid & 7;
        const int jg2 = (tid >> 3) & 1;
        const int pt2 = (tid >> 4) & 3;
        const int jh  = tid >> 7;
        ull acc2[4][4];
#pragma unroll
        for (int j = 0; j < 4; j++)
#pragma unroll
            for (int cp = 0; cp < 4; cp++) acc2[j][cp] = 0ULL;

        const float* aB = aS + (pt2*16 + jg2*8 + jh*4)*68;
        const float* wB = wS + cg2*8;
#pragma unroll 2
        for (int k4 = 0; k4 < 64; k4 += 4) {
            float4 av[4];
#pragma unroll
            for (int j = 0; j < 4; j++)
                av[j] = *reinterpret_cast<const float4*>(aB + j*68 + k4);
#pragma unroll
            for (int kk = 0; kk < 4; kk++) {
                const float* wrow = wB + (k4+kk)*68;
                ulonglong2 w01 = *reinterpret_cast<const ulonglong2*>(wrow);
                ulonglong2 w23 = *reinterpret_cast<const ulonglong2*>(wrow + 4);
#pragma unroll
                for (int j = 0; j < 4; j++) {
                    const float* af = (const float*)&av[j];
                    float a = af[kk];
                    ull ad = pack2(a, a);
                    ffma2(acc2[j][0], ad, w01.x);
                    ffma2(acc2[j][1], ad, w01.y);
                    ffma2(acc2[j][2], ad, w23.x);
                    ffma2(acc2[j][3], ad, w23.y);
                }
            }
        }
        float* y2 = aS + 4352;
        int base = pt2*1024 + (jg2*8 + jh*4)*64 + cg2*8;
#pragma unroll
        for (int j = 0; j < 4; j++) {
#pragma unroll
            for (int cp = 0; cp < 4; cp++) {
                float lo, hi;
                unpack2(lo, hi, acc2[j][cp]);
                int c = cg2*8 + cp*2;
                *reinterpret_cast<float2*>(&y2[base + j*64 + cp*2]) =
                    make_float2(lo + b2[c], hi + b2[c+1]);
            }
        }
    }
    __syncthreads();

    // ---- softmax over 16 neighbors per (pt, c) ----
    {
        float* y2 = aS + 4352;
        int ptc = tid >> 6;
        int c   = tid & 63;
        float* col = y2 + ptc*1024 + c;
        float mx = -3.4e38f;
#pragma unroll
        for (int j = 0; j < NS; j++) mx = fmaxf(mx, col[j*64]);
        float ex[NS];
        float sum = 0.0f;
#pragma unroll
        for (int j = 0; j < NS; j++) {
            ex[j] = expf(col[j*64] - mx);
            sum += ex[j];
        }
        float inv = 1.0f / sum;
#pragma unroll
        for (int j = 0; j < NS; j++) col[j*64] = ex[j] * inv;
    }
    __syncthreads();

    // ---- epilogue (float4 across cf) ----
    {
        const float* y2 = aS + 4352;
#pragma unroll
        for (int i = 0; i < 2; i++) {
            int s = tid + i*256;
            int ptb = s >> 7;
            int cf  = (s & 127) * 4;
            int cc  = cf & 63;
            float4 q0 = *reinterpret_cast<const float4*>(&p2W[cf]);
            float4 q1 = *reinterpret_cast<const float4*>(&p2W[CC + cf]);
            float4 q2 = *reinterpret_cast<const float4*>(&p2W[2*CC + cf]);
            float4 qb = *reinterpret_cast<const float4*>(&p2b[cf]);
            const float* ybase = y2 + ptb*1024 + cc;
            const int* idxp = idxS + ptb*16;
            const float* hp = hS + ptb*48;
            float4 acco = make_float4(0.f, 0.f, 0.f, 0.f);
#pragma unroll
            for (int j = 0; j < NS; j++) {
                int m = idxp[j];
                float h0 = hp[j*3+0], h1 = hp[j*3+1], h2 = hp[j*3+2];
                float4 xv4 = *reinterpret_cast<const float4*>(&g_xv[(size_t)(b*NN+m)*CC + cf]);
                float4 w4  = *reinterpret_cast<const float4*>(ybase + j*64);
                float pr;
                pr = h0*q0.x + h1*q1.x + h2*q2.x + qb.x;
                acco.x = fmaf(xv4.x + pr, w4.x, acco.x);
                pr = h0*q0.y + h1*q1.y + h2*q2.y + qb.y;
                acco.y = fmaf(xv4.y + pr, w4.y, acco.y);
                pr = h0*q0.z + h1*q1.z + h2*q2.z + qb.z;
                acco.z = fmaf(xv4.z + pr, w4.z, acco.z);
                pr = h0*q0.w + h1*q1.w + h2*q2.w + qb.w;
                acco.w = fmaf(xv4.w + pr, w4.w, acco.w);
            }
            *reinterpret_cast<float4*>(&out[(size_t)(row0+ptb)*CC + cf]) = acco;
        }
    }
}

// ============================ launcher =======================================
extern "C" void kernel_launch(void* const* d_in, const int* in_sizes, int n_in,
                              void* d_out, int out_size)
{
    const float* p    = (const float*)d_in[0];
    const float* x    = (const float*)d_in[1];
    const float* Wq   = (const float*)d_in[2];
    const float* bq   = (const float*)d_in[3];
    const float* Wk   = (const float*)d_in[4];
    const float* bk   = (const float*)d_in[5];
    const float* Wv   = (const float*)d_in[6];
    const float* bv   = (const float*)d_in[7];
    const float* p1W  = (const float*)d_in[8];
    const float* p1b  = (const float*)d_in[9];
    const float* pbng = (const float*)d_in[10];
    const float* pbnb = (const float*)d_in[11];
    const float* p2W  = (const float*)d_in[12];
    const float* p2b  = (const float*)d_in[13];
    const float* bn1g = (const float*)d_in[14];
    const float* bn1b = (const float*)d_in[15];
    const float* W1   = (const float*)d_in[16];
    const float* b1   = (const float*)d_in[17];
    const float* bn2g = (const float*)d_in[18];
    const float* bn2b = (const float*)d_in[19];
    const float* W2   = (const float*)d_in[20];
    const float* b2   = (const float*)d_in[21];
    float* out = (float*)d_out;

    cudaFuncSetAttribute(pt_main, cudaFuncAttributeMaxDynamicSharedMemorySize,
                         SM_TOT * sizeof(float));

    stage1_kernel<<<QKV_BLOCKS + BB*64, 256>>>(p, x, Wq, bq, Wk, bk, Wv, bv);
    pt_main<<<ROWS/4, 256, SM_TOT * sizeof(float)>>>(
        p, p1W, p1b, pbng, pbnb, p2W, p2b,
        bn1g, bn1b, W1, b1, bn2g, bn2b, W2, b2, out);
}

// round 13
// speedup vs baseline: 1.5617x; 1.5617x over previous
#include <cuda_runtime.h>
#include <math.h>

#define BB 16
#define NN 512
#define CC 512
#define NS 16
#define CM 64           // CC / S
#define ROWS (BB*NN)    // 8192

typedef unsigned long long ull;

__device__ __forceinline__ void ffma2(ull &d, ull a, ull b) {
    asm("fma.rn.f32x2 %0, %1, %2, %0;" : "+l"(d) : "l"(a), "l"(b));
}
__device__ __forceinline__ ull pack2(float lo, float hi) {
    ull r; asm("mov.b64 %0, {%1, %2};" : "=l"(r) : "f"(lo), "f"(hi)); return r;
}
__device__ __forceinline__ void unpack2(float &lo, float &hi, ull v) {
    asm("mov.b64 {%0, %1}, %2;" : "=f"(lo), "=f"(hi) : "l"(v));
}

// ---------------- scratch (static device globals; no allocation) -------------
__device__ float g_xq[ROWS*CC];
__device__ float g_xk[ROWS*CC];
__device__ float g_xv[ROWS*CC];
__device__ int   g_idx[ROWS*NS];

// ================= stage1: fused QKV GEMM + kNN in one launch ================
#define QKV_BLOCKS 768

__global__ __launch_bounds__(256) void stage1_kernel(
    const float* __restrict__ p,
    const float* __restrict__ x,
    const float* __restrict__ Wq, const float* __restrict__ bq,
    const float* __restrict__ Wk, const float* __restrict__ bk,
    const float* __restrict__ Wv, const float* __restrict__ bv)
{
    __shared__ __align__(16) float smem_u[2 * 16 * 132];

    if (blockIdx.x < QKV_BLOCKS) {
        float (*As)[132] = reinterpret_cast<float(*)[132]>(smem_u);
        float (*Bs)[132] = reinterpret_cast<float(*)[132]>(smem_u + 16*132);

        const int z    = blockIdx.x >> 8;
        const int tile = blockIdx.x & 255;
        const float* W; const float* bias; float* out;
        if (z == 0)      { W = Wq; bias = bq; out = g_xq; }
        else if (z == 1) { W = Wk; bias = bk; out = g_xk; }
        else             { W = Wv; bias = bv; out = g_xv; }

        const int tid = threadIdx.x;
        const int tx = tid & 15;
        const int ty = tid >> 4;
        const int m0 = (tile >> 2) * 128;
        const int c0 = (tile & 3) * 128;
        const int b  = m0 >> 9;
        const int n0 = m0 & 511;
        const float* xb = x + (size_t)b * CC * NN;

        ull acc[8][4];
#pragma unroll
        for (int i = 0; i < 8; i++)
#pragma unroll
            for (int j = 0; j < 4; j++) acc[i][j] = 0ULL;

        for (int k0 = 0; k0 < CC; k0 += 16) {
#pragma unroll
            for (int i = 0; i < 2; i++) {
                int f  = tid + i*256;
                int kk = f >> 5;
                int mm = (f & 31) * 4;
                *reinterpret_cast<float4*>(&As[kk][mm]) =
                    *reinterpret_cast<const float4*>(&xb[(size_t)(k0+kk)*NN + n0 + mm]);
                *reinterpret_cast<float4*>(&Bs[kk][mm]) =
                    *reinterpret_cast<const float4*>(&W[(size_t)(k0+kk)*CC + c0 + mm]);
            }
            __syncthreads();
#pragma unroll
            for (int kk = 0; kk < 16; kk++) {
                float4 a0 = *reinterpret_cast<const float4*>(&As[kk][ty*4]);
                float4 a1 = *reinterpret_cast<const float4*>(&As[kk][64 + ty*4]);
                ulonglong2 bp01 = *reinterpret_cast<const ulonglong2*>(&Bs[kk][tx*4]);
                ulonglong2 bp23 = *reinterpret_cast<const ulonglong2*>(&Bs[kk][64 + tx*4]);
                float av[8] = {a0.x,a0.y,a0.z,a0.w, a1.x,a1.y,a1.z,a1.w};
#pragma unroll
                for (int i = 0; i < 8; i++) {
                    ull ad = pack2(av[i], av[i]);
                    ffma2(acc[i][0], ad, bp01.x);
                    ffma2(acc[i][1], ad, bp01.y);
                    ffma2(acc[i][2], ad, bp23.x);
                    ffma2(acc[i][3], ad, bp23.y);
                }
            }
            __syncthreads();
        }

#pragma unroll
        for (int i = 0; i < 8; i++) {
            int row = m0 + ((i < 4) ? (ty*4 + i) : (64 + ty*4 + i - 4));
#pragma unroll
            for (int jh = 0; jh < 2; jh++) {
                int c = c0 + ((jh == 0) ? (tx*4) : (64 + tx*4));
                float e0,e1,e2,e3;
                unpack2(e0, e1, acc[i][jh*2+0]);
                unpack2(e2, e3, acc[i][jh*2+1]);
                float4 v;
                v.x = e0 + bias[c+0];
                v.y = e1 + bias[c+1];
                v.z = e2 + bias[c+2];
                v.w = e3 + bias[c+3];
                *reinterpret_cast<float4*>(&out[(size_t)row*CC + c]) = v;
            }
        }
    } else {
        // kNN: warp per query; ulp-exact distances
        float* ps = smem_u;
        float* sq = smem_u + NN*3;
        const int kb   = blockIdx.x - QKV_BLOCKS;
        const int b    = kb >> 6;
        const int warp = threadIdx.x >> 5;
        const int lane = threadIdx.x & 31;
        const float* pb = p + (size_t)b * NN * 3;
        for (int i = threadIdx.x; i < NN*3; i += 256) ps[i] = pb[i];
        __syncthreads();
        for (int i = threadIdx.x; i < NN; i += 256) {
            float m0 = __fmul_rn(ps[i*3+0], ps[i*3+0]);
            float m1 = __fmul_rn(ps[i*3+1], ps[i*3+1]);
            float m2 = __fmul_rn(ps[i*3+2], ps[i*3+2]);
            sq[i] = __fadd_rn(__fadd_rn(m0, m1), m2);
        }
        __syncthreads();

        const int n = (kb & 63) * 8 + warp;
        const float px = ps[n*3+0], py = ps[n*3+1], pz = ps[n*3+2];
        const float sn = sq[n];

        float d[16];
#pragma unroll
        for (int i = 0; i < 16; i++) {
            int m = lane * 16 + i;
            float dot = __fmul_rn(px, ps[m*3+0]);
            dot = fmaf(py, ps[m*3+1], dot);
            dot = fmaf(pz, ps[m*3+2], dot);
            d[i] = __fsub_rn(__fadd_rn(sn, sq[m]), __fmul_rn(2.0f, dot));
        }

        const int row = b*NN + n;
        const float INF = __int_as_float(0x7f800000);
#pragma unroll 1
        for (int t = 0; t < NS; t++) {
            float bd = d[0]; int bi = 0;
#pragma unroll
            for (int i = 1; i < 16; i++) if (d[i] < bd) { bd = d[i]; bi = i; }
            int ib = __float_as_int(bd);
            unsigned u = (unsigned)ib ^ ((ib < 0) ? 0xFFFFFFFFu : 0x80000000u);
            ull key = ((ull)u << 32) | (unsigned)(lane*16 + bi);
#pragma unroll
            for (int s = 16; s > 0; s >>= 1) {
                ull o = __shfl_xor_sync(0xFFFFFFFFu, key, s);
                if (o < key) key = o;
            }
            int win_m = (int)(key & 0xFFFFFFFFu);
            if ((win_m >> 4) == lane) {
                int wi = win_m & 15;
#pragma unroll
                for (int i = 0; i < 16; i++) if (i == wi) d[i] = INF;
            }
            if (lane == 0) g_idx[row*NS + t] = win_m;
        }
    }
}

// ============================ main fused kernel ==============================
// 4 points per block, 2048 blocks, 256 threads, 2 blocks/SM.
// Round-7 structure; W1/W2 read DIRECTLY from global (L1-resident, no staging).
// Smem (floats):
//   aS [0, 8448)     : 64 x 132 a-chunk; later partial slices 0/1, then a2
//   pS [8448,16896)  : partial slices 2/3; later y2 (softmax weights)
//   xq [16896,18944) : 4 x 512
//   b1s[18944,19456), b1o[19456,19968)
//   hS [19968,20160), idx[20160,20224)
#define SM_AS   0
#define SM_PS   8448
#define SM_XQ   16896
#define SM_B1S  18944
#define SM_B1O  19456
#define SM_H    19968
#define SM_IDX  20160
#define SM_TOT  20224   // floats -> 80896 bytes

__global__ __launch_bounds__(256, 2) void pt_main(
    const float* __restrict__ p,
    const float* __restrict__ p1W,  const float* __restrict__ p1b,
    const float* __restrict__ pbng, const float* __restrict__ pbnb,
    const float* __restrict__ p2W,  const float* __restrict__ p2b,
    const float* __restrict__ bn1g, const float* __restrict__ bn1bv,
    const float* __restrict__ W1,   const float* __restrict__ b1,
    const float* __restrict__ bn2g, const float* __restrict__ bn2bv,
    const float* __restrict__ W2,   const float* __restrict__ b2,
    float* __restrict__ out)
{
    extern __shared__ __align__(16) float sm[];
    float* aS   = sm + SM_AS;
    float* pS   = sm + SM_PS;
    float* xqS  = sm + SM_XQ;
    float* b1sS = sm + SM_B1S;
    float* b1oS = sm + SM_B1O;
    float* hS   = sm + SM_H;
    int*   idxS = (int*)(sm + SM_IDX);

    const int tid  = threadIdx.x;
    const int row0 = blockIdx.x * 4;
    const int b    = row0 >> 9;
    const float RS = rsqrtf(1.0f + 1e-5f);

    // ---- prologue ----
    if (tid < 64) {
        int pt = tid >> 4;
        int row = row0 + pt;
        int m = g_idx[row*NS + (tid & 15)];
        idxS[tid] = m;
        int gm = b*NN + m;
        float prx = p[gm*3+0] - p[row*3+0];
        float pry = p[gm*3+1] - p[row*3+1];
        float prz = p[gm*3+2] - p[row*3+2];
#pragma unroll
        for (int j = 0; j < 3; j++) {
            float v = prx*p1W[0*3+j] + pry*p1W[1*3+j] + prz*p1W[2*3+j] + p1b[j];
            v = v * (pbng[j] * RS) + pbnb[j];
            hS[tid*3+j] = fmaxf(v, 0.0f);
        }
    }
#pragma unroll
    for (int i = 0; i < 2; i++) {
        int s = tid + i*256;
        int pt = s >> 7, c4 = (s & 127) * 4;
        *reinterpret_cast<float4*>(&xqS[pt*512 + c4]) =
            *reinterpret_cast<const float4*>(&g_xq[(size_t)(row0+pt)*CC + c4]);
    }
#pragma unroll
    for (int i = 0; i < 2; i++) {
        int c = tid + i*256;
        b1sS[c] = bn1g[c] * RS;
        b1oS[c] = bn1bv[c];
    }
    __syncthreads();

    // GEMM1 mapping: cg(8c) x jg(2 of 8j) x pt(4) x ks(4 of 32k)
    const int cg = tid & 7;
    const int jg = (tid >> 3) & 1;
    const int pt = (tid >> 4) & 3;
    const int ks = tid >> 6;

    ull acc[8][4];
#pragma unroll
    for (int j = 0; j < 8; j++)
#pragma unroll
        for (int cp = 0; cp < 4; cp++) acc[j][cp] = 0ULL;

    for (int kc = 0; kc < 4; kc++) {
        // phase B chunk: aS[r][k] = relu(bn1(xk - xq + pr)), 64 rows x 128 k
#pragma unroll
        for (int i = 0; i < 8; i++) {
            int s = tid + i*256;
            int r = s >> 5, k4 = (s & 31) * 4;
            int c = kc*128 + k4;
            int ptb = r >> 4;
            int m  = idxS[r];
            float h0 = hS[r*3+0], h1 = hS[r*3+1], h2 = hS[r*3+2];
            float4 xk4 = *reinterpret_cast<const float4*>(&g_xk[(size_t)(b*NN+m)*CC + c]);
            float4 q04 = *reinterpret_cast<const float4*>(&p2W[c]);
            float4 q14 = *reinterpret_cast<const float4*>(&p2W[CC + c]);
            float4 q24 = *reinterpret_cast<const float4*>(&p2W[2*CC + c]);
            float4 pb4 = *reinterpret_cast<const float4*>(&p2b[c]);
            float4 xq4 = *reinterpret_cast<const float4*>(&xqS[ptb*512 + c]);
            float4 s14 = *reinterpret_cast<const float4*>(&b1sS[c]);
            float4 o14 = *reinterpret_cast<const float4*>(&b1oS[c]);
            float4 res;
            {
                float pr = h0*q04.x + h1*q14.x + h2*q24.x + pb4.x;
                res.x = fmaxf(fmaf(xk4.x - xq4.x + pr, s14.x, o14.x), 0.0f);
                pr = h0*q04.y + h1*q14.y + h2*q24.y + pb4.y;
                res.y = fmaxf(fmaf(xk4.y - xq4.y + pr, s14.y, o14.y), 0.0f);
                pr = h0*q04.z + h1*q14.z + h2*q24.z + pb4.z;
                res.z = fmaxf(fmaf(xk4.z - xq4.z + pr, s14.z, o14.z), 0.0f);
                pr = h0*q04.w + h1*q14.w + h2*q24.w + pb4.w;
                res.w = fmaxf(fmaf(xk4.w - xq4.w + pr, s14.w, o14.w), 0.0f);
            }
            *reinterpret_cast<float4*>(&aS[r*132 + k4]) = res;
        }
        __syncthreads();

        // GEMM1 chunk: acc += a(8j x 32k-slice) @ W1(32k x 8c), W1 from GLOBAL
        {
            const float* aB = aS + (pt*16 + jg*8)*132 + ks*32;
            const float* wB = W1 + (size_t)(kc*128 + ks*32)*CM + cg*8;
#pragma unroll 2
            for (int k4 = 0; k4 < 32; k4 += 4) {
                float4 av[8];
#pragma unroll
                for (int j = 0; j < 8; j++)
                    av[j] = *reinterpret_cast<const float4*>(aB + j*132 + k4);
#pragma unroll
                for (int kk = 0; kk < 4; kk++) {
                    const float* wrow = wB + (size_t)(k4+kk)*CM;
                    ulonglong2 w01 = *reinterpret_cast<const ulonglong2*>(wrow);
                    ulonglong2 w23 = *reinterpret_cast<const ulonglong2*>(wrow + 4);
#pragma unroll
                    for (int j = 0; j < 8; j++) {
                        const float* af = (const float*)&av[j];
                        float a = af[kk];
                        ull ad = pack2(a, a);
                        ffma2(acc[j][0], ad, w01.x);
                        ffma2(acc[j][1], ad, w01.y);
                        ffma2(acc[j][2], ad, w23.x);
                        ffma2(acc[j][3], ad, w23.y);
                    }
                }
            }
        }
        __syncthreads();
    }

    // spill partials: ks 0/1 -> aS, ks 2/3 -> pS
    {
        float* dst = ((ks < 2) ? aS : pS) + (ks & 1) * 4096;
        int base = pt*1024 + jg*8*64 + cg*8;
#pragma unroll
        for (int j = 0; j < 8; j++) {
#pragma unroll
            for (int cp = 0; cp < 4; cp++) {
                float lo, hi;
                unpack2(lo, hi, acc[j][cp]);
                *reinterpret_cast<float2*>(&dst[base + j*64 + cp*2]) =
                    make_float2(lo, hi);
            }
        }
    }
    __syncthreads();

    // reduce 4 slices + bias + bn2 + relu
    float a2v[16];
#pragma unroll
    for (int i = 0; i < 16; i++) {
        int o = tid + i*256;
        int c = o & 63;
        float s = aS[o] + aS[4096 + o] + pS[o] + pS[4096 + o];
        s += b1[c];
        s = fmaf(s, bn2g[c]*RS, bn2bv[c]);
        a2v[i] = fmaxf(s, 0.0f);
    }
    __syncthreads();

    // write a2 (stride 68 rows in aS)
#pragma unroll
    for (int i = 0; i < 16; i++) {
        int o = tid + i*256;
        int r = o >> 6, c = o & 63;
        aS[r*68 + c] = a2v[i];
    }
    __syncthreads();

    // ---- GEMM2: (64 rows x 64k) @ (64k x 64c); W2 from GLOBAL ----
    {
        const int cg2 = tid & 7;
        const int jg2 = (tid >> 3) & 1;
        const int pt2 = (tid >> 4) & 3;
        const int jh  = tid >> 7;
        ull acc2[4][4];
#pragma unroll
        for (int j = 0; j < 4; j++)
#pragma unroll
            for (int cp = 0; cp < 4; cp++) acc2[j][cp] = 0ULL;

        const float* aB = aS + (pt2*16 + jg2*8 + jh*4)*68;
        const float* wB = W2 + cg2*8;
#pragma unroll 2
        for (int k4 = 0; k4 < 64; k4 += 4) {
            float4 av[4];
#pragma unroll
            for (int j = 0; j < 4; j++)
                av[j] = *reinterpret_cast<const float4*>(aB + j*68 + k4);
#pragma unroll
            for (int kk = 0; kk < 4; kk++) {
                const float* wrow = wB + (size_t)(k4+kk)*CM;
                ulonglong2 w01 = *reinterpret_cast<const ulonglong2*>(wrow);
                ulonglong2 w23 = *reinterpret_cast<const ulonglong2*>(wrow + 4);
#pragma unroll
                for (int j = 0; j < 4; j++) {
                    const float* af = (const float*)&av[j];
                    float a = af[kk];
                    ull ad = pack2(a, a);
                    ffma2(acc2[j][0], ad, w01.x);
                    ffma2(acc2[j][1], ad, w01.y);
                    ffma2(acc2[j][2], ad, w23.x);
                    ffma2(acc2[j][3], ad, w23.y);
                }
            }
        }
        float* y2 = pS;
        int base = pt2*1024 + (jg2*8 + jh*4)*64 + cg2*8;
#pragma unroll
        for (int j = 0; j < 4; j++) {
#pragma unroll
            for (int cp = 0; cp < 4; cp++) {
                float lo, hi;
                unpack2(lo, hi, acc2[j][cp]);
                int c = cg2*8 + cp*2;
                *reinterpret_cast<float2*>(&y2[base + j*64 + cp*2]) =
                    make_float2(lo + b2[c], hi + b2[c+1]);
            }
        }
    }
    __syncthreads();

    // ---- softmax over 16 neighbors per (pt, c) ----
    {
        float* y2 = pS;
        int ptc = tid >> 6;
        int c   = tid & 63;
        float* col = y2 + ptc*1024 + c;
        float mx = -3.4e38f;
#pragma unroll
        for (int j = 0; j < NS; j++) mx = fmaxf(mx, col[j*64]);
        float ex[NS];
        float sum = 0.0f;
#pragma unroll
        for (int j = 0; j < NS; j++) {
            ex[j] = expf(col[j*64] - mx);
            sum += ex[j];
        }
        float inv = 1.0f / sum;
#pragma unroll
        for (int j = 0; j < NS; j++) col[j*64] = ex[j] * inv;
    }
    __syncthreads();

    // ---- epilogue (float4 across cf) ----
    {
        const float* y2 = pS;
#pragma unroll
        for (int i = 0; i < 2; i++) {
            int s = tid + i*256;
            int ptb = s >> 7;
            int cf  = (s & 127) * 4;
            int cc  = cf & 63;
            float4 q0 = *reinterpret_cast<const float4*>(&p2W[cf]);
            float4 q1 = *reinterpret_cast<const float4*>(&p2W[CC + cf]);
            float4 q2 = *reinterpret_cast<const float4*>(&p2W[2*CC + cf]);
            float4 qb = *reinterpret_cast<const float4*>(&p2b[cf]);
            const float* ybase = y2 + ptb*1024 + cc;
            const int* idxp = idxS + ptb*16;
            const float* hp = hS + ptb*48;
            float4 acco = make_float4(0.f, 0.f, 0.f, 0.f);
#pragma unroll
            for (int j = 0; j < NS; j++) {
                int m = idxp[j];
                float h0 = hp[j*3+0], h1 = hp[j*3+1], h2 = hp[j*3+2];
                float4 xv4 = *reinterpret_cast<const float4*>(&g_xv[(size_t)(b*NN+m)*CC + cf]);
                float4 w4  = *reinterpret_cast<const float4*>(ybase + j*64);
                float pr;
                pr = h0*q0.x + h1*q1.x + h2*q2.x + qb.x;
                acco.x = fmaf(xv4.x + pr, w4.x, acco.x);
                pr = h0*q0.y + h1*q1.y + h2*q2.y + qb.y;
                acco.y = fmaf(xv4.y + pr, w4.y, acco.y);
                pr = h0*q0.z + h1*q1.z + h2*q2.z + qb.z;
                acco.z = fmaf(xv4.z + pr, w4.z, acco.z);
                pr = h0*q0.w + h1*q1.w + h2*q2.w + qb.w;
                acco.w = fmaf(xv4.w + pr, w4.w, acco.w);
            }
            *reinterpret_cast<float4*>(&out[(size_t)(row0+ptb)*CC + cf]) = acco;
        }
    }
}

// ============================ launcher =======================================
extern "C" void kernel_launch(void* const* d_in, const int* in_sizes, int n_in,
                              void* d_out, int out_size)
{
    const float* p    = (const float*)d_in[0];
    const float* x    = (const float*)d_in[1];
    const float* Wq   = (const float*)d_in[2];
    const float* bq   = (const float*)d_in[3];
    const float* Wk   = (const float*)d_in[4];
    const float* bk   = (const float*)d_in[5];
    const float* Wv   = (const float*)d_in[6];
    const float* bv   = (const float*)d_in[7];
    const float* p1W  = (const float*)d_in[8];
    const float* p1b  = (const float*)d_in[9];
    const float* pbng = (const float*)d_in[10];
    const float* pbnb = (const float*)d_in[11];
    const float* p2W  = (const float*)d_in[12];
    const float* p2b  = (const float*)d_in[13];
    const float* bn1g = (const float*)d_in[14];
    const float* bn1b = (const float*)d_in[15];
    const float* W1   = (const float*)d_in[16];
    const float* b1   = (const float*)d_in[17];
    const float* bn2g = (const float*)d_in[18];
    const float* bn2b = (const float*)d_in[19];
    const float* W2   = (const float*)d_in[20];
    const float* b2   = (const float*)d_in[21];
    float* out = (float*)d_out;

    cudaFuncSetAttribute(pt_main, cudaFuncAttributeMaxDynamicSharedMemorySize,
                         SM_TOT * sizeof(float));

    stage1_kernel<<<QKV_BLOCKS + BB*64, 256>>>(p, x, Wq, bq, Wk, bk, Wv, bv);
    pt_main<<<ROWS/4, 256, SM_TOT * sizeof(float)>>>(
        p, p1W, p1b, pbng, pbnb, p2W, p2b,
        bn1g, bn1b, W1, b1, bn2g, bn2b, W2, b2, out);
}

// round 14
// speedup vs baseline: 1.5924x; 1.0197x over previous
#include <cuda_runtime.h>
#include <math.h>

#define BB 16
#define NN 512
#define CC 512
#define NS 16
#define CM 64           // CC / S
#define ROWS (BB*NN)    // 8192

typedef unsigned long long ull;

__device__ __forceinline__ void ffma2(ull &d, ull a, ull b) {
    asm("fma.rn.f32x2 %0, %1, %2, %0;" : "+l"(d) : "l"(a), "l"(b));
}
__device__ __forceinline__ ull pack2(float lo, float hi) {
    ull r; asm("mov.b64 %0, {%1, %2};" : "=l"(r) : "f"(lo), "f"(hi)); return r;
}
__device__ __forceinline__ void unpack2(float &lo, float &hi, ull v) {
    asm("mov.b64 {%0, %1}, %2;" : "=f"(lo), "=f"(hi) : "l"(v));
}

// ---------------- scratch (static device globals; no allocation) -------------
__device__ float g_xq[ROWS*CC];
__device__ float g_xk[ROWS*CC];
__device__ float g_xv[ROWS*CC];
__device__ int   g_idx[ROWS*NS];

// ================= stage1: fused QKV GEMM + kNN in one launch ================
#define QKV_BLOCKS 768

__global__ __launch_bounds__(256) void stage1_kernel(
    const float* __restrict__ p,
    const float* __restrict__ x,
    const float* __restrict__ Wq, const float* __restrict__ bq,
    const float* __restrict__ Wk, const float* __restrict__ bk,
    const float* __restrict__ Wv, const float* __restrict__ bv)
{
    __shared__ __align__(16) float smem_u[2 * 2 * 16 * 132];   // 33.8 KB union

    if (blockIdx.x < QKV_BLOCKS) {
        // double-buffered 128x128 tile GEMM, BK=16, FFMA2
        float (*As)[16][132] = reinterpret_cast<float(*)[16][132]>(smem_u);
        float (*Bs)[16][132] = reinterpret_cast<float(*)[16][132]>(smem_u + 2*16*132);

        const int z    = blockIdx.x >> 8;
        const int tile = blockIdx.x & 255;
        const float* W; const float* bias; float* out;
        if (z == 0)      { W = Wq; bias = bq; out = g_xq; }
        else if (z == 1) { W = Wk; bias = bk; out = g_xk; }
        else             { W = Wv; bias = bv; out = g_xv; }

        const int tid = threadIdx.x;
        const int tx = tid & 15;
        const int ty = tid >> 4;
        const int m0 = (tile >> 2) * 128;
        const int c0 = (tile & 3) * 128;
        const int b  = m0 >> 9;
        const int n0 = m0 & 511;
        const float* xb = x + (size_t)b * CC * NN;

        // per-thread load indices (2 float4 per array per slab)
        int lkk[2], lmm[2];
#pragma unroll
        for (int i = 0; i < 2; i++) {
            int f  = tid + i*256;
            lkk[i] = f >> 5;
            lmm[i] = (f & 31) * 4;
        }

        ull acc[8][4];
#pragma unroll
        for (int i = 0; i < 8; i++)
#pragma unroll
            for (int j = 0; j < 4; j++) acc[i][j] = 0ULL;

        // preload slab 0
#pragma unroll
        for (int i = 0; i < 2; i++) {
            *reinterpret_cast<float4*>(&As[0][lkk[i]][lmm[i]]) =
                *reinterpret_cast<const float4*>(&xb[(size_t)lkk[i]*NN + n0 + lmm[i]]);
            *reinterpret_cast<float4*>(&Bs[0][lkk[i]][lmm[i]]) =
                *reinterpret_cast<const float4*>(&W[(size_t)lkk[i]*CC + c0 + lmm[i]]);
        }
        __syncthreads();

        for (int s = 0; s < 32; s++) {
            const int cb = s & 1;
            float4 ra[2], rb[2];
            if (s < 31) {
                int k0 = (s+1) * 16;
#pragma unroll
                for (int i = 0; i < 2; i++) {
                    ra[i] = *reinterpret_cast<const float4*>(
                        &xb[(size_t)(k0+lkk[i])*NN + n0 + lmm[i]]);
                    rb[i] = *reinterpret_cast<const float4*>(
                        &W[(size_t)(k0+lkk[i])*CC + c0 + lmm[i]]);
                }
            }
#pragma unroll
            for (int kk = 0; kk < 16; kk++) {
                float4 a0 = *reinterpret_cast<const float4*>(&As[cb][kk][ty*4]);
                float4 a1 = *reinterpret_cast<const float4*>(&As[cb][kk][64 + ty*4]);
                ulonglong2 bp01 = *reinterpret_cast<const ulonglong2*>(&Bs[cb][kk][tx*4]);
                ulonglong2 bp23 = *reinterpret_cast<const ulonglong2*>(&Bs[cb][kk][64 + tx*4]);
                float av[8] = {a0.x,a0.y,a0.z,a0.w, a1.x,a1.y,a1.z,a1.w};
#pragma unroll
                for (int i = 0; i < 8; i++) {
                    ull ad = pack2(av[i], av[i]);
                    ffma2(acc[i][0], ad, bp01.x);
                    ffma2(acc[i][1], ad, bp01.y);
                    ffma2(acc[i][2], ad, bp23.x);
                    ffma2(acc[i][3], ad, bp23.y);
                }
            }
            if (s < 31) {
                const int nb = cb ^ 1;
#pragma unroll
                for (int i = 0; i < 2; i++) {
                    *reinterpret_cast<float4*>(&As[nb][lkk[i]][lmm[i]]) = ra[i];
                    *reinterpret_cast<float4*>(&Bs[nb][lkk[i]][lmm[i]]) = rb[i];
                }
            }
            __syncthreads();
        }

#pragma unroll
        for (int i = 0; i < 8; i++) {
            int row = m0 + ((i < 4) ? (ty*4 + i) : (64 + ty*4 + i - 4));
#pragma unroll
            for (int jh = 0; jh < 2; jh++) {
                int c = c0 + ((jh == 0) ? (tx*4) : (64 + tx*4));
                float e0,e1,e2,e3;
                unpack2(e0, e1, acc[i][jh*2+0]);
                unpack2(e2, e3, acc[i][jh*2+1]);
                float4 v;
                v.x = e0 + bias[c+0];
                v.y = e1 + bias[c+1];
                v.z = e2 + bias[c+2];
                v.w = e3 + bias[c+3];
                *reinterpret_cast<float4*>(&out[(size_t)row*CC + c]) = v;
            }
        }
    } else {
        // kNN: warp per query; ulp-exact distances
        float* ps = smem_u;
        float* sq = smem_u + NN*3;
        const int kb   = blockIdx.x - QKV_BLOCKS;
        const int b    = kb >> 6;
        const int warp = threadIdx.x >> 5;
        const int lane = threadIdx.x & 31;
        const float* pb = p + (size_t)b * NN * 3;
        for (int i = threadIdx.x; i < NN*3; i += 256) ps[i] = pb[i];
        __syncthreads();
        for (int i = threadIdx.x; i < NN; i += 256) {
            float m0 = __fmul_rn(ps[i*3+0], ps[i*3+0]);
            float m1 = __fmul_rn(ps[i*3+1], ps[i*3+1]);
            float m2 = __fmul_rn(ps[i*3+2], ps[i*3+2]);
            sq[i] = __fadd_rn(__fadd_rn(m0, m1), m2);
        }
        __syncthreads();

        const int n = (kb & 63) * 8 + warp;
        const float px = ps[n*3+0], py = ps[n*3+1], pz = ps[n*3+2];
        const float sn = sq[n];

        float d[16];
#pragma unroll
        for (int i = 0; i < 16; i++) {
            int m = lane * 16 + i;
            float dot = __fmul_rn(px, ps[m*3+0]);
            dot = fmaf(py, ps[m*3+1], dot);
            dot = fmaf(pz, ps[m*3+2], dot);
            d[i] = __fsub_rn(__fadd_rn(sn, sq[m]), __fmul_rn(2.0f, dot));
        }

        const int row = b*NN + n;
        const float INF = __int_as_float(0x7f800000);
#pragma unroll 1
        for (int t = 0; t < NS; t++) {
            float bd = d[0]; int bi = 0;
#pragma unroll
            for (int i = 1; i < 16; i++) if (d[i] < bd) { bd = d[i]; bi = i; }
            int ib = __float_as_int(bd);
            unsigned u = (unsigned)ib ^ ((ib < 0) ? 0xFFFFFFFFu : 0x80000000u);
            ull key = ((ull)u << 32) | (unsigned)(lane*16 + bi);
#pragma unroll
            for (int s = 16; s > 0; s >>= 1) {
                ull o = __shfl_xor_sync(0xFFFFFFFFu, key, s);
                if (o < key) key = o;
            }
            int win_m = (int)(key & 0xFFFFFFFFu);
            if ((win_m >> 4) == lane) {
                int wi = win_m & 15;
#pragma unroll
                for (int i = 0; i < 16; i++) if (i == wi) d[i] = INF;
            }
            if (lane == 0) g_idx[row*NS + t] = win_m;
        }
    }
}

// ============================ main fused kernel ==============================
// 4 points per block, 2048 blocks, 256 threads, 2 blocks/SM.
// W1/W2 direct from global; a-chunks PING-PONG between aS and pS so phase-B
// gathers of chunk kc+1 overlap GEMM1 compute of chunk kc (one barrier/chunk).
#define SM_AS   0
#define SM_PS   8448
#define SM_XQ   16896
#define SM_B1S  18944
#define SM_B1O  19456
#define SM_H    19968
#define SM_IDX  20160
#define SM_TOT  20224   // floats -> 80896 bytes

__global__ __launch_bounds__(256, 2) void pt_main(
    const float* __restrict__ p,
    const float* __restrict__ p1W,  const float* __restrict__ p1b,
    const float* __restrict__ pbng, const float* __restrict__ pbnb,
    const float* __restrict__ p2W,  const float* __restrict__ p2b,
    const float* __restrict__ bn1g, const float* __restrict__ bn1bv,
    const float* __restrict__ W1,   const float* __restrict__ b1,
    const float* __restrict__ bn2g, const float* __restrict__ bn2bv,
    const float* __restrict__ W2,   const float* __restrict__ b2,
    float* __restrict__ out)
{
    extern __shared__ __align__(16) float sm[];
    float* aS   = sm + SM_AS;
    float* pS   = sm + SM_PS;
    float* xqS  = sm + SM_XQ;
    float* b1sS = sm + SM_B1S;
    float* b1oS = sm + SM_B1O;
    float* hS   = sm + SM_H;
    int*   idxS = (int*)(sm + SM_IDX);

    const int tid  = threadIdx.x;
    const int row0 = blockIdx.x * 4;
    const int b    = row0 >> 9;
    const float RS = rsqrtf(1.0f + 1e-5f);

    // ---- prologue ----
    if (tid < 64) {
        int pt = tid >> 4;
        int row = row0 + pt;
        int m = g_idx[row*NS + (tid & 15)];
        idxS[tid] = m;
        int gm = b*NN + m;
        float prx = p[gm*3+0] - p[row*3+0];
        float pry = p[gm*3+1] - p[row*3+1];
        float prz = p[gm*3+2] - p[row*3+2];
#pragma unroll
        for (int j = 0; j < 3; j++) {
            float v = prx*p1W[0*3+j] + pry*p1W[1*3+j] + prz*p1W[2*3+j] + p1b[j];
            v = v * (pbng[j] * RS) + pbnb[j];
            hS[tid*3+j] = fmaxf(v, 0.0f);
        }
    }
#pragma unroll
    for (int i = 0; i < 2; i++) {
        int s = tid + i*256;
        int pt = s >> 7, c4 = (s & 127) * 4;
        *reinterpret_cast<float4*>(&xqS[pt*512 + c4]) =
            *reinterpret_cast<const float4*>(&g_xq[(size_t)(row0+pt)*CC + c4]);
    }
#pragma unroll
    for (int i = 0; i < 2; i++) {
        int c = tid + i*256;
        b1sS[c] = bn1g[c] * RS;
        b1oS[c] = bn1bv[c];
    }
    __syncthreads();

    // GEMM1 mapping: cg(8c) x jg(2 of 8j) x pt(4) x ks(4 of 32k)
    const int cg = tid & 7;
    const int jg = (tid >> 3) & 1;
    const int pt = (tid >> 4) & 3;
    const int ks = tid >> 6;

    // phase B producer (writes 64 rows x 128 k of chunk kc into buf)
    auto phaseB = [&](int kc, float* buf) {
#pragma unroll
        for (int i = 0; i < 8; i++) {
            int s = tid + i*256;
            int r = s >> 5, k4 = (s & 31) * 4;
            int c = kc*128 + k4;
            int ptb = r >> 4;
            int m  = idxS[r];
            float h0 = hS[r*3+0], h1 = hS[r*3+1], h2 = hS[r*3+2];
            float4 xk4 = *reinterpret_cast<const float4*>(&g_xk[(size_t)(b*NN+m)*CC + c]);
            float4 q04 = *reinterpret_cast<const float4*>(&p2W[c]);
            float4 q14 = *reinterpret_cast<const float4*>(&p2W[CC + c]);
            float4 q24 = *reinterpret_cast<const float4*>(&p2W[2*CC + c]);
            float4 pb4 = *reinterpret_cast<const float4*>(&p2b[c]);
            float4 xq4 = *reinterpret_cast<const float4*>(&xqS[ptb*512 + c]);
            float4 s14 = *reinterpret_cast<const float4*>(&b1sS[c]);
            float4 o14 = *reinterpret_cast<const float4*>(&b1oS[c]);
            float4 res;
            {
                float pr = h0*q04.x + h1*q14.x + h2*q24.x + pb4.x;
                res.x = fmaxf(fmaf(xk4.x - xq4.x + pr, s14.x, o14.x), 0.0f);
                pr = h0*q04.y + h1*q14.y + h2*q24.y + pb4.y;
                res.y = fmaxf(fmaf(xk4.y - xq4.y + pr, s14.y, o14.y), 0.0f);
                pr = h0*q04.z + h1*q14.z + h2*q24.z + pb4.z;
                res.z = fmaxf(fmaf(xk4.z - xq4.z + pr, s14.z, o14.z), 0.0f);
                pr = h0*q04.w + h1*q14.w + h2*q24.w + pb4.w;
                res.w = fmaxf(fmaf(xk4.w - xq4.w + pr, s14.w, o14.w), 0.0f);
            }
            *reinterpret_cast<float4*>(&buf[r*132 + k4]) = res;
        }
    };

    ull acc[8][4];
#pragma unroll
    for (int j = 0; j < 8; j++)
#pragma unroll
        for (int cp = 0; cp < 4; cp++) acc[j][cp] = 0ULL;

    // pipeline: fill buf0, then overlap phaseB(kc+1) with GEMM1(kc)
    phaseB(0, aS);
    __syncthreads();

#pragma unroll 1
    for (int kc = 0; kc < 4; kc++) {
        float* cur = (kc & 1) ? pS : aS;
        float* nxt = (kc & 1) ? aS : pS;
        if (kc < 3) phaseB(kc+1, nxt);

        // GEMM1 chunk: acc += a(8j x 32k-slice) @ W1(32k x 8c), W1 from GLOBAL
        {
            const float* aB = cur + (pt*16 + jg*8)*132 + ks*32;
            const float* wB = W1 + (size_t)(kc*128 + ks*32)*CM + cg*8;
#pragma unroll 2
            for (int k4 = 0; k4 < 32; k4 += 4) {
                float4 av[8];
#pragma unroll
                for (int j = 0; j < 8; j++)
                    av[j] = *reinterpret_cast<const float4*>(aB + j*132 + k4);
#pragma unroll
                for (int kk = 0; kk < 4; kk++) {
                    const float* wrow = wB + (size_t)(k4+kk)*CM;
                    ulonglong2 w01 = *reinterpret_cast<const ulonglong2*>(wrow);
                    ulonglong2 w23 = *reinterpret_cast<const ulonglong2*>(wrow + 4);
#pragma unroll
                    for (int j = 0; j < 8; j++) {
                        const float* af = (const float*)&av[j];
                        float a = af[kk];
                        ull ad = pack2(a, a);
                        ffma2(acc[j][0], ad, w01.x);
                        ffma2(acc[j][1], ad, w01.y);
                        ffma2(acc[j][2], ad, w23.x);
                        ffma2(acc[j][3], ad, w23.y);
                    }
                }
            }
        }
        __syncthreads();
    }

    // spill partials: ks 0/1 -> aS, ks 2/3 -> pS
    {
        float* dst = ((ks < 2) ? aS : pS) + (ks & 1) * 4096;
        int base = pt*1024 + jg*8*64 + cg*8;
#pragma unroll
        for (int j = 0; j < 8; j++) {
#pragma unroll
            for (int cp = 0; cp < 4; cp++) {
                float lo, hi;
                unpack2(lo, hi, acc[j][cp]);
                *reinterpret_cast<float2*>(&dst[base + j*64 + cp*2]) =
                    make_float2(lo, hi);
            }
        }
    }
    __syncthreads();

    // reduce 4 slices + bias + bn2 + relu
    float a2v[16];
#pragma unroll
    for (int i = 0; i < 16; i++) {
        int o = tid + i*256;
        int c = o & 63;
        float s = aS[o] + aS[4096 + o] + pS[o] + pS[4096 + o];
        s += b1[c];
        s = fmaf(s, bn2g[c]*RS, bn2bv[c]);
        a2v[i] = fmaxf(s, 0.0f);
    }
    __syncthreads();

    // write a2 (stride 68 rows in aS)
#pragma unroll
    for (int i = 0; i < 16; i++) {
        int o = tid + i*256;
        int r = o >> 6, c = o & 63;
        aS[r*68 + c] = a2v[i];
    }
    __syncthreads();

    // ---- GEMM2: (64 rows x 64k) @ (64k x 64c); W2 from GLOBAL ----
    {
        const int cg2 = tid & 7;
        const int jg2 = (tid >> 3) & 1;
        const int pt2 = (tid >> 4) & 3;
        const int jh  = tid >> 7;
        ull acc2[4][4];
#pragma unroll
        for (int j = 0; j < 4; j++)
#pragma unroll
            for (int cp = 0; cp < 4; cp++) acc2[j][cp] = 0ULL;

        const float* aB = aS + (pt2*16 + jg2*8 + jh*4)*68;
        const float* wB = W2 + cg2*8;
#pragma unroll 2
        for (int k4 = 0; k4 < 64; k4 += 4) {
            float4 av[4];
#pragma unroll
            for (int j = 0; j < 4; j++)
                av[j] = *reinterpret_cast<const float4*>(aB + j*68 + k4);
#pragma unroll
            for (int kk = 0; kk < 4; kk++) {
                const float* wrow = wB + (size_t)(k4+kk)*CM;
                ulonglong2 w01 = *reinterpret_cast<const ulonglong2*>(wrow);
                ulonglong2 w23 = *reinterpret_cast<const ulonglong2*>(wrow + 4);
#pragma unroll
                for (int j = 0; j < 4; j++) {
                    const float* af = (const float*)&av[j];
                    float a = af[kk];
                    ull ad = pack2(a, a);
                    ffma2(acc2[j][0], ad, w01.x);
                    ffma2(acc2[j][1], ad, w01.y);
                    ffma2(acc2[j][2], ad, w23.x);
                    ffma2(acc2[j][3], ad, w23.y);
                }
            }
        }
        float* y2 = pS;
        int base = pt2*1024 + (jg2*8 + jh*4)*64 + cg2*8;
#pragma unroll
        for (int j = 0; j < 4; j++) {
#pragma unroll
            for (int cp = 0; cp < 4; cp++) {
                float lo, hi;
                unpack2(lo, hi, acc2[j][cp]);
                int c = cg2*8 + cp*2;
                *reinterpret_cast<float2*>(&y2[base + j*64 + cp*2]) =
                    make_float2(lo + b2[c], hi + b2[c+1]);
            }
        }
    }
    __syncthreads();

    // ---- softmax over 16 neighbors per (pt, c) ----
    {
        float* y2 = pS;
        int ptc = tid >> 6;
        int c   = tid & 63;
        float* col = y2 + ptc*1024 + c;
        float mx = -3.4e38f;
#pragma unroll
        for (int j = 0; j < NS; j++) mx = fmaxf(mx, col[j*64]);
        float ex[NS];
        float sum = 0.0f;
#pragma unroll
        for (int j = 0; j < NS; j++) {
            ex[j] = expf(col[j*64] - mx);
            sum += ex[j];
        }
        float inv = 1.0f / sum;
#pragma unroll
        for (int j = 0; j < NS; j++) col[j*64] = ex[j] * inv;
    }
    __syncthreads();

    // ---- epilogue (float4 across cf) ----
    {
        const float* y2 = pS;
#pragma unroll
        for (int i = 0; i < 2; i++) {
            int s = tid + i*256;
            int ptb = s >> 7;
            int cf  = (s & 127) * 4;
            int cc  = cf & 63;
            float4 q0 = *reinterpret_cast<const float4*>(&p2W[cf]);
            float4 q1 = *reinterpret_cast<const float4*>(&p2W[CC + cf]);
            float4 q2 = *reinterpret_cast<const float4*>(&p2W[2*CC + cf]);
            float4 qb = *reinterpret_cast<const float4*>(&p2b[cf]);
            const float* ybase = y2 + ptb*1024 + cc;
            const int* idxp = idxS + ptb*16;
            const float* hp = hS + ptb*48;
            float4 acco = make_float4(0.f, 0.f, 0.f, 0.f);
#pragma unroll
            for (int j = 0; j < NS; j++) {
                int m = idxp[j];
                float h0 = hp[j*3+0], h1 = hp[j*3+1], h2 = hp[j*3+2];
                float4 xv4 = *reinterpret_cast<const float4*>(&g_xv[(size_t)(b*NN+m)*CC + cf]);
                float4 w4  = *reinterpret_cast<const float4*>(ybase + j*64);
                float pr;
                pr = h0*q0.x + h1*q1.x + h2*q2.x + qb.x;
                acco.x = fmaf(xv4.x + pr, w4.x, acco.x);
                pr = h0*q0.y + h1*q1.y + h2*q2.y + qb.y;
                acco.y = fmaf(xv4.y + pr, w4.y, acco.y);
                pr = h0*q0.z + h1*q1.z + h2*q2.z + qb.z;
                acco.z = fmaf(xv4.z + pr, w4.z, acco.z);
                pr = h0*q0.w + h1*q1.w + h2*q2.w + qb.w;
                acco.w = fmaf(xv4.w + pr, w4.w, acco.w);
            }
            *reinterpret_cast<float4*>(&out[(size_t)(row0+ptb)*CC + cf]) = acco;
        }
    }
}

// ============================ launcher =======================================
extern "C" void kernel_launch(void* const* d_in, const int* in_sizes, int n_in,
                              void* d_out, int out_size)
{
    const float* p    = (const float*)d_in[0];
    const float* x    = (const float*)d_in[1];
    const float* Wq   = (const float*)d_in[2];
    const float* bq   = (const float*)d_in[3];
    const float* Wk   = (const float*)d_in[4];
    const float* bk   = (const float*)d_in[5];
    const float* Wv   = (const float*)d_in[6];
    const float* bv   = (const float*)d_in[7];
    const float* p1W  = (const float*)d_in[8];
    const float* p1b  = (const float*)d_in[9];
    const float* pbng = (const float*)d_in[10];
    const float* pbnb = (const float*)d_in[11];
    const float* p2W  = (const float*)d_in[12];
    const float* p2b  = (const float*)d_in[13];
    const float* bn1g = (const float*)d_in[14];
    const float* bn1b = (const float*)d_in[15];
    const float* W1   = (const float*)d_in[16];
    const float* b1   = (const float*)d_in[17];
    const float* bn2g = (const float*)d_in[18];
    const float* bn2b = (const float*)d_in[19];
    const float* W2   = (const float*)d_in[20];
    const float* b2   = (const float*)d_in[21];
    float* out = (float*)d_out;

    cudaFuncSetAttribute(pt_main, cudaFuncAttributeMaxDynamicSharedMemorySize,
                         SM_TOT * sizeof(float));

    stage1_kernel<<<QKV_BLOCKS + BB*64, 256>>>(p, x, Wq, bq, Wk, bk, Wv, bv);
    pt_main<<<ROWS/4, 256, SM_TOT * sizeof(float)>>>(
        p, p1W, p1b, pbng, pbnb, p2W, p2b,
        bn1g, bn1b, W1, b1, bn2g, bn2b, W2, b2, out);
}